// round 1
// baseline (speedup 1.0000x reference)
#include <cuda_runtime.h>
#include <cstdint>

#define HB   32
#define IND  64
#define OUTD 64

typedef unsigned long long u64;

// ---------- packed f32x2 helpers (sm_103a) ----------
__device__ __forceinline__ u64 pk2(float lo, float hi) {
    u64 r;
    asm("mov.b64 %0, {%1, %2};"
        : "=l"(r) : "r"(__float_as_uint(lo)), "r"(__float_as_uint(hi)));
    return r;
}
__device__ __forceinline__ void upk2(float& lo, float& hi, u64 v) {
    unsigned a, b;
    asm("mov.b64 {%0, %1}, %2;" : "=r"(a), "=r"(b) : "l"(v));
    lo = __uint_as_float(a);
    hi = __uint_as_float(b);
}
#define FMA2(d, a, b, c) asm("fma.rn.f32x2 %0, %1, %2, %3;" : "=l"(d) : "l"(a), "l"(b), "l"(c))
#define ADD2(d, a, b)    asm("add.rn.f32x2 %0, %1, %2;"     : "=l"(d) : "l"(a), "l"(b))
#define MUL2(d, a, b)    asm("mul.rn.f32x2 %0, %1, %2;"     : "=l"(d) : "l"(a), "l"(b))

// ---------- folded parameters ----------
// A  = w1 @ (I + g1*wv1)                [64,32] row-major [k][j]
// ab = b1 @ (I + g1*wv1) + g1*bv1       [32]
// C  = w2 @ (I + g2*wv2)                [32,32]
// cb = b2 @ (I + g2*wv2) + g2*bv2       [32]
// WO = wo                               [32,64]
struct __align__(16) Params {
    float A[IND * HB];
    float ab[HB];
    float C[HB * HB];
    float cb[HB];
    float WO[HB * OUTD];
    float bo[OUTD];
    float l1g[HB];
    float l1b[HB];
    float l2g[HB];
    float l2b[HB];
};
__device__ Params g_params;

// ---------- prep: fold attention into the linear layers ----------
__global__ void prep_kernel(
    const float* __restrict__ w1,  const float* __restrict__ b1,
    const float* __restrict__ wv1, const float* __restrict__ bv1,
    const float* __restrict__ g1,
    const float* __restrict__ l1g, const float* __restrict__ l1b,
    const float* __restrict__ w2,  const float* __restrict__ b2,
    const float* __restrict__ wv2, const float* __restrict__ bv2,
    const float* __restrict__ g2,
    const float* __restrict__ l2g, const float* __restrict__ l2b,
    const float* __restrict__ wo,  const float* __restrict__ bo)
{
    const int t = threadIdx.x;
    const float g1v = g1[0];
    const float g2v = g2[0];

    // A[i][j] = w1[i][j] + g1 * sum_m w1[i][m] * wv1[m][j]
    for (int idx = t; idx < IND * HB; idx += blockDim.x) {
        int i = idx >> 5, j = idx & 31;
        float s = 0.0f;
        for (int m = 0; m < HB; m++) s += w1[i * HB + m] * wv1[m * HB + j];
        g_params.A[idx] = w1[i * HB + j] + g1v * s;
    }
    // C[i][j] = w2[i][j] + g2 * sum_m w2[i][m] * wv2[m][j]
    for (int idx = t; idx < HB * HB; idx += blockDim.x) {
        int i = idx >> 5, j = idx & 31;
        float s = 0.0f;
        for (int m = 0; m < HB; m++) s += w2[i * HB + m] * wv2[m * HB + j];
        g_params.C[idx] = w2[i * HB + j] + g2v * s;
    }
    if (t < HB) {
        int j = t;
        float s1 = 0.0f, s2 = 0.0f;
        for (int m = 0; m < HB; m++) {
            s1 += b1[m] * wv1[m * HB + j];
            s2 += b2[m] * wv2[m * HB + j];
        }
        g_params.ab[j] = b1[j] + g1v * (s1 + bv1[j]);
        g_params.cb[j] = b2[j] + g2v * (s2 + bv2[j]);
        g_params.l1g[j] = l1g[j];
        g_params.l1b[j] = l1b[j];
        g_params.l2g[j] = l2g[j];
        g_params.l2b[j] = l2b[j];
    }
    for (int idx = t; idx < HB * OUTD; idx += blockDim.x) g_params.WO[idx] = wo[idx];
    for (int idx = t; idx < OUTD; idx += blockDim.x) g_params.bo[idx] = bo[idx];
}

// ---------- layernorm + leaky-relu on 16 packed channel-pairs ----------
__device__ __forceinline__ void ln_leaky(const u64* t2, const u64* g2s, const u64* b2s,
                                         float* y)
{
    u64 s2 = t2[0];
#pragma unroll
    for (int p = 1; p < 16; p++) ADD2(s2, s2, t2[p]);
    u64 q2;
    MUL2(q2, t2[0], t2[0]);
#pragma unroll
    for (int p = 1; p < 16; p++) FMA2(q2, t2[p], t2[p], q2);

    float sl, sh, ql, qh;
    upk2(sl, sh, s2);
    upk2(ql, qh, q2);
    const float m   = (sl + sh) * (1.0f / HB);
    const float var = fmaf(-m, m, (ql + qh) * (1.0f / HB));
    const float r   = rsqrtf(var + 1e-5f);
    const u64 rr = pk2(r, r);
    const u64 cc = pk2(-m * r, -m * r);

#pragma unroll
    for (int p = 0; p < 16; p++) {
        u64 n2, y2;
        FMA2(n2, t2[p], rr, cc);      // (t - m) * rsqrt(var+eps)
        FMA2(y2, n2, g2s[p], b2s[p]); // * gamma + beta
        float a, b;
        upk2(a, b, y2);
        // leaky_relu(y) == max(y, 0.01*y) for all finite y
        y[2 * p]     = fmaxf(a, 0.01f * a);
        y[2 * p + 1] = fmaxf(b, 0.01f * b);
    }
}

// ---------- main fused kernel: one thread per batch row ----------
__global__ void __launch_bounds__(256)
fused_kernel(const float* __restrict__ x, float* __restrict__ out, int B)
{
    __shared__ Params sp;
    {
        const float4* s = reinterpret_cast<const float4*>(&g_params);
        float4* d = reinterpret_cast<float4*>(&sp);
        for (int i = threadIdx.x; i < (int)(sizeof(Params) / 16); i += 256) d[i] = s[i];
    }
    __syncthreads();

    const int row = blockIdx.x * 256 + threadIdx.x;
    if (row >= B) return;

    // load x row (64 floats)
    float xr[IND];
    {
        const float4* xp = reinterpret_cast<const float4*>(x + (size_t)row * IND);
#pragma unroll
        for (int i = 0; i < IND / 4; i++) {
            float4 v = xp[i];
            xr[4 * i + 0] = v.x;
            xr[4 * i + 1] = v.y;
            xr[4 * i + 2] = v.z;
            xr[4 * i + 3] = v.w;
        }
    }

    // ---- layer 1 (+ folded attn1): t = x @ A + ab ----
    u64 t2[16];
    {
        const u64* ab2 = reinterpret_cast<const u64*>(sp.ab);
#pragma unroll
        for (int p = 0; p < 16; p++) t2[p] = ab2[p];
#pragma unroll
        for (int k = 0; k < IND; k++) {
            const u64 xd = pk2(xr[k], xr[k]);
            const ulonglong2* wr = reinterpret_cast<const ulonglong2*>(sp.A + k * HB);
#pragma unroll
            for (int q = 0; q < 8; q++) {
                ulonglong2 w = wr[q];
                FMA2(t2[2 * q + 0], xd, w.x, t2[2 * q + 0]);
                FMA2(t2[2 * q + 1], xd, w.y, t2[2 * q + 1]);
            }
        }
    }

    // ---- LN1 + leaky ----
    float y[HB];
    ln_leaky(t2, reinterpret_cast<const u64*>(sp.l1g),
             reinterpret_cast<const u64*>(sp.l1b), y);

    // ---- layer 2 (+ folded attn2): u = y @ C + cb ----
    u64 u2[16];
    {
        const u64* cb2 = reinterpret_cast<const u64*>(sp.cb);
#pragma unroll
        for (int p = 0; p < 16; p++) u2[p] = cb2[p];
#pragma unroll
        for (int k = 0; k < HB; k++) {
            const u64 xd = pk2(y[k], y[k]);
            const ulonglong2* wr = reinterpret_cast<const ulonglong2*>(sp.C + k * HB);
#pragma unroll
            for (int q = 0; q < 8; q++) {
                ulonglong2 w = wr[q];
                FMA2(u2[2 * q + 0], xd, w.x, u2[2 * q + 0]);
                FMA2(u2[2 * q + 1], xd, w.y, u2[2 * q + 1]);
            }
        }
    }

    // ---- LN2 + leaky ----
    float z[HB];
    ln_leaky(u2, reinterpret_cast<const u64*>(sp.l2g),
             reinterpret_cast<const u64*>(sp.l2b), z);

    // ---- output layer: o = z @ WO + bo ----
    u64 o2[32];
    {
        const u64* bo2 = reinterpret_cast<const u64*>(sp.bo);
#pragma unroll
        for (int p = 0; p < 32; p++) o2[p] = bo2[p];
#pragma unroll
        for (int k = 0; k < HB; k++) {
            const u64 xd = pk2(z[k], z[k]);
            const ulonglong2* wr = reinterpret_cast<const ulonglong2*>(sp.WO + k * OUTD);
#pragma unroll
            for (int q = 0; q < 16; q++) {
                ulonglong2 w = wr[q];
                FMA2(o2[2 * q + 0], xd, w.x, o2[2 * q + 0]);
                FMA2(o2[2 * q + 1], xd, w.y, o2[2 * q + 1]);
            }
        }
    }

    // store row (packed pairs are exactly out[2p], out[2p+1])
    ulonglong2* op = reinterpret_cast<ulonglong2*>(out + (size_t)row * OUTD);
#pragma unroll
    for (int q = 0; q < 16; q++) {
        ulonglong2 v;
        v.x = o2[2 * q + 0];
        v.y = o2[2 * q + 1];
        op[q] = v;
    }
}

// ---------- launch ----------
extern "C" void kernel_launch(void* const* d_in, const int* in_sizes, int n_in,
                              void* d_out, int out_size)
{
    const float* x    = (const float*)d_in[0];
    const float* w1   = (const float*)d_in[1];
    const float* b1   = (const float*)d_in[2];
    // d_in[3..6] = wq1,bq1,wk1,bk1 : dead (softmax over T=1 is identity)
    const float* wv1  = (const float*)d_in[7];
    const float* bv1  = (const float*)d_in[8];
    const float* g1   = (const float*)d_in[9];
    const float* l1g  = (const float*)d_in[10];
    const float* l1b  = (const float*)d_in[11];
    const float* w2   = (const float*)d_in[12];
    const float* b2   = (const float*)d_in[13];
    // d_in[14..17] = wq2,bq2,wk2,bk2 : dead
    const float* wv2  = (const float*)d_in[18];
    const float* bv2  = (const float*)d_in[19];
    const float* g2   = (const float*)d_in[20];
    const float* l2g  = (const float*)d_in[21];
    const float* l2b  = (const float*)d_in[22];
    const float* wo   = (const float*)d_in[23];
    const float* bo   = (const float*)d_in[24];

    const int B = in_sizes[0] / IND;

    prep_kernel<<<1, 256>>>(w1, b1, wv1, bv1, g1, l1g, l1b,
                            w2, b2, wv2, bv2, g2, l2g, l2b, wo, bo);

    const int blocks = (B + 255) / 256;
    fused_kernel<<<blocks, 256>>>(x, (float*)d_out, B);
}

// round 2
// speedup vs baseline: 1.0016x; 1.0016x over previous
#include <cuda_runtime.h>
#include <cstdint>

#define HB   32
#define IND  64
#define OUTD 64

typedef unsigned long long u64;

// ---------- packed f32x2 helpers (sm_103a) ----------
__device__ __forceinline__ u64 pk2(float lo, float hi) {
    u64 r;
    asm("mov.b64 %0, {%1, %2};"
        : "=l"(r) : "r"(__float_as_uint(lo)), "r"(__float_as_uint(hi)));
    return r;
}
__device__ __forceinline__ void upk2(float& lo, float& hi, u64 v) {
    unsigned a, b;
    asm("mov.b64 {%0, %1}, %2;" : "=r"(a), "=r"(b) : "l"(v));
    lo = __uint_as_float(a);
    hi = __uint_as_float(b);
}
#define FMA2(d, a, b, c) asm("fma.rn.f32x2 %0, %1, %2, %3;" : "=l"(d) : "l"(a), "l"(b), "l"(c))
#define ADD2(d, a, b)    asm("add.rn.f32x2 %0, %1, %2;"     : "=l"(d) : "l"(a), "l"(b))
#define MUL2(d, a, b)    asm("mul.rn.f32x2 %0, %1, %2;"     : "=l"(d) : "l"(a), "l"(b))

// ---------- folded parameters ----------
// A  = w1 @ (I + g1*wv1)                [64,32] row-major [k][j]
// ab = b1 @ (I + g1*wv1) + g1*bv1       [32]
// C  = w2 @ (I + g2*wv2)                [32,32]
// cb = b2 @ (I + g2*wv2) + g2*bv2       [32]
// WO = wo                               [32,64]
struct __align__(16) Params {
    float A[IND * HB];
    float ab[HB];
    float C[HB * HB];
    float cb[HB];
    float WO[HB * OUTD];
    float bo[OUTD];
    float l1g[HB];
    float l1b[HB];
    float l2g[HB];
    float l2b[HB];
};
__device__ Params g_params;

// ---------- prep: fold attention into the linear layers ----------
__global__ void prep_kernel(
    const float* __restrict__ w1,  const float* __restrict__ b1,
    const float* __restrict__ wv1, const float* __restrict__ bv1,
    const float* __restrict__ g1,
    const float* __restrict__ l1g, const float* __restrict__ l1b,
    const float* __restrict__ w2,  const float* __restrict__ b2,
    const float* __restrict__ wv2, const float* __restrict__ bv2,
    const float* __restrict__ g2,
    const float* __restrict__ l2g, const float* __restrict__ l2b,
    const float* __restrict__ wo,  const float* __restrict__ bo)
{
    const int t = threadIdx.x;
    const float g1v = g1[0];
    const float g2v = g2[0];

    // A[i][j] = w1[i][j] + g1 * sum_m w1[i][m] * wv1[m][j]
    for (int idx = t; idx < IND * HB; idx += blockDim.x) {
        int i = idx >> 5, j = idx & 31;
        float s = 0.0f;
        for (int m = 0; m < HB; m++) s += w1[i * HB + m] * wv1[m * HB + j];
        g_params.A[idx] = w1[i * HB + j] + g1v * s;
    }
    // C[i][j] = w2[i][j] + g2 * sum_m w2[i][m] * wv2[m][j]
    for (int idx = t; idx < HB * HB; idx += blockDim.x) {
        int i = idx >> 5, j = idx & 31;
        float s = 0.0f;
        for (int m = 0; m < HB; m++) s += w2[i * HB + m] * wv2[m * HB + j];
        g_params.C[idx] = w2[i * HB + j] + g2v * s;
    }
    if (t < HB) {
        int j = t;
        float s1 = 0.0f, s2 = 0.0f;
        for (int m = 0; m < HB; m++) {
            s1 += b1[m] * wv1[m * HB + j];
            s2 += b2[m] * wv2[m * HB + j];
        }
        g_params.ab[j] = b1[j] + g1v * (s1 + bv1[j]);
        g_params.cb[j] = b2[j] + g2v * (s2 + bv2[j]);
        g_params.l1g[j] = l1g[j];
        g_params.l1b[j] = l1b[j];
        g_params.l2g[j] = l2g[j];
        g_params.l2b[j] = l2b[j];
    }
    for (int idx = t; idx < HB * OUTD; idx += blockDim.x) g_params.WO[idx] = wo[idx];
    for (int idx = t; idx < OUTD; idx += blockDim.x) g_params.bo[idx] = bo[idx];
}

// ---------- layernorm + leaky-relu on 16 packed channel-pairs ----------
__device__ __forceinline__ void ln_leaky(const u64* t2, const u64* g2s, const u64* b2s,
                                         float* y)
{
    u64 s2 = t2[0];
#pragma unroll
    for (int p = 1; p < 16; p++) ADD2(s2, s2, t2[p]);
    u64 q2;
    MUL2(q2, t2[0], t2[0]);
#pragma unroll
    for (int p = 1; p < 16; p++) FMA2(q2, t2[p], t2[p], q2);

    float sl, sh, ql, qh;
    upk2(sl, sh, s2);
    upk2(ql, qh, q2);
    const float m   = (sl + sh) * (1.0f / HB);
    const float var = fmaf(-m, m, (ql + qh) * (1.0f / HB));
    const float r   = rsqrtf(var + 1e-5f);
    const u64 rr = pk2(r, r);
    const u64 cc = pk2(-m * r, -m * r);

#pragma unroll
    for (int p = 0; p < 16; p++) {
        u64 n2, y2;
        FMA2(n2, t2[p], rr, cc);      // (t - m) * rsqrt(var+eps)
        FMA2(y2, n2, g2s[p], b2s[p]); // * gamma + beta
        float a, b;
        upk2(a, b, y2);
        // leaky_relu(y) == max(y, 0.01*y) for all finite y
        y[2 * p]     = fmaxf(a, 0.01f * a);
        y[2 * p + 1] = fmaxf(b, 0.01f * b);
    }
}

// ---------- main fused kernel: one thread per batch row ----------
__global__ void __launch_bounds__(256)
fused_kernel(const float* __restrict__ x, float* __restrict__ out, int B)
{
    __shared__ Params sp;
    {
        const float4* s = reinterpret_cast<const float4*>(&g_params);
        float4* d = reinterpret_cast<float4*>(&sp);
        for (int i = threadIdx.x; i < (int)(sizeof(Params) / 16); i += 256) d[i] = s[i];
    }
    __syncthreads();

    const int row = blockIdx.x * 256 + threadIdx.x;
    if (row >= B) return;

    // load x row (64 floats)
    float xr[IND];
    {
        const float4* xp = reinterpret_cast<const float4*>(x + (size_t)row * IND);
#pragma unroll
        for (int i = 0; i < IND / 4; i++) {
            float4 v = xp[i];
            xr[4 * i + 0] = v.x;
            xr[4 * i + 1] = v.y;
            xr[4 * i + 2] = v.z;
            xr[4 * i + 3] = v.w;
        }
    }

    // ---- layer 1 (+ folded attn1): t = x @ A + ab ----
    u64 t2[16];
    {
        const u64* ab2 = reinterpret_cast<const u64*>(sp.ab);
#pragma unroll
        for (int p = 0; p < 16; p++) t2[p] = ab2[p];
#pragma unroll
        for (int k = 0; k < IND; k++) {
            const u64 xd = pk2(xr[k], xr[k]);
            const ulonglong2* wr = reinterpret_cast<const ulonglong2*>(sp.A + k * HB);
#pragma unroll
            for (int q = 0; q < 8; q++) {
                ulonglong2 w = wr[q];
                FMA2(t2[2 * q + 0], xd, w.x, t2[2 * q + 0]);
                FMA2(t2[2 * q + 1], xd, w.y, t2[2 * q + 1]);
            }
        }
    }

    // ---- LN1 + leaky ----
    float y[HB];
    ln_leaky(t2, reinterpret_cast<const u64*>(sp.l1g),
             reinterpret_cast<const u64*>(sp.l1b), y);

    // ---- layer 2 (+ folded attn2): u = y @ C + cb ----
    u64 u2[16];
    {
        const u64* cb2 = reinterpret_cast<const u64*>(sp.cb);
#pragma unroll
        for (int p = 0; p < 16; p++) u2[p] = cb2[p];
#pragma unroll
        for (int k = 0; k < HB; k++) {
            const u64 xd = pk2(y[k], y[k]);
            const ulonglong2* wr = reinterpret_cast<const ulonglong2*>(sp.C + k * HB);
#pragma unroll
            for (int q = 0; q < 8; q++) {
                ulonglong2 w = wr[q];
                FMA2(u2[2 * q + 0], xd, w.x, u2[2 * q + 0]);
                FMA2(u2[2 * q + 1], xd, w.y, u2[2 * q + 1]);
            }
        }
    }

    // ---- LN2 + leaky ----
    float z[HB];
    ln_leaky(u2, reinterpret_cast<const u64*>(sp.l2g),
             reinterpret_cast<const u64*>(sp.l2b), z);

    // ---- output layer: o = z @ WO + bo ----
    u64 o2[32];
    {
        const u64* bo2 = reinterpret_cast<const u64*>(sp.bo);
#pragma unroll
        for (int p = 0; p < 32; p++) o2[p] = bo2[p];
#pragma unroll
        for (int k = 0; k < HB; k++) {
            const u64 xd = pk2(z[k], z[k]);
            const ulonglong2* wr = reinterpret_cast<const ulonglong2*>(sp.WO + k * OUTD);
#pragma unroll
            for (int q = 0; q < 16; q++) {
                ulonglong2 w = wr[q];
                FMA2(o2[2 * q + 0], xd, w.x, o2[2 * q + 0]);
                FMA2(o2[2 * q + 1], xd, w.y, o2[2 * q + 1]);
            }
        }
    }

    // store row (packed pairs are exactly out[2p], out[2p+1])
    ulonglong2* op = reinterpret_cast<ulonglong2*>(out + (size_t)row * OUTD);
#pragma unroll
    for (int q = 0; q < 16; q++) {
        ulonglong2 v;
        v.x = o2[2 * q + 0];
        v.y = o2[2 * q + 1];
        op[q] = v;
    }
}

// ---------- launch ----------
extern "C" void kernel_launch(void* const* d_in, const int* in_sizes, int n_in,
                              void* d_out, int out_size)
{
    const float* x    = (const float*)d_in[0];
    const float* w1   = (const float*)d_in[1];
    const float* b1   = (const float*)d_in[2];
    // d_in[3..6] = wq1,bq1,wk1,bk1 : dead (softmax over T=1 is identity)
    const float* wv1  = (const float*)d_in[7];
    const float* bv1  = (const float*)d_in[8];
    const float* g1   = (const float*)d_in[9];
    const float* l1g  = (const float*)d_in[10];
    const float* l1b  = (const float*)d_in[11];
    const float* w2   = (const float*)d_in[12];
    const float* b2   = (const float*)d_in[13];
    // d_in[14..17] = wq2,bq2,wk2,bk2 : dead
    const float* wv2  = (const float*)d_in[18];
    const float* bv2  = (const float*)d_in[19];
    const float* g2   = (const float*)d_in[20];
    const float* l2g  = (const float*)d_in[21];
    const float* l2b  = (const float*)d_in[22];
    const float* wo   = (const float*)d_in[23];
    const float* bo   = (const float*)d_in[24];

    const int B = in_sizes[0] / IND;

    prep_kernel<<<1, 256>>>(w1, b1, wv1, bv1, g1, l1g, l1b,
                            w2, b2, wv2, bv2, g2, l2g, l2b, wo, bo);

    const int blocks = (B + 255) / 256;
    fused_kernel<<<blocks, 256>>>(x, (float*)d_out, B);
}

// round 4
// speedup vs baseline: 2.9462x; 2.9415x over previous
#include <cuda_runtime.h>
#include <cstdint>

typedef uint32_t u32;

// pack two f32 -> bf16x2 (lo arg in low half), RN
__device__ __forceinline__ u32 pkbf(float lo, float hi) {
    u32 r; asm("cvt.rn.bf16x2.f32 %0, %1, %2;" : "=r"(r) : "f"(hi), "f"(lo)); return r;
}
__device__ __forceinline__ float bflo(u32 h) { return __uint_as_float(h << 16); }
__device__ __forceinline__ float bfhi(u32 h) { return __uint_as_float(h & 0xFFFF0000u); }
// hi/lo bf16 split of a float pair
__device__ __forceinline__ void split2(float a, float b, u32& hp, u32& lp) {
    hp = pkbf(a, b);
    lp = pkbf(a - bflo(hp), b - bfhi(hp));
}

#define MMA(d, a0, a1, a2, a3, b0, b1)                                      \
    asm volatile("mma.sync.aligned.m16n8k16.row.col.f32.bf16.bf16.f32 "     \
                 "{%0,%1,%2,%3},{%4,%5,%6,%7},{%8,%9},{%0,%1,%2,%3};"       \
                 : "+f"((d)[0]), "+f"((d)[1]), "+f"((d)[2]), "+f"((d)[3])   \
                 : "r"(a0), "r"(a1), "r"(a2), "r"(a3), "r"(b0), "r"(b1))

// Weight fragments, pre-arranged per-lane: uint4 = {hi_b0, hi_b1, lo_b0, lo_b1}
struct __align__(16) WBlob {
    uint4 w1[4][4][32];   // GEMM1: K=64 (4 kfrags) x N=32 (4 nfrags)
    uint4 w2[2][4][32];   // GEMM2: K=32 x N=32
    uint4 w3[2][8][32];   // GEMM3: K=32 x N=64
    float ab[32], cb[32], bo[64];
    float l1g[32], l1b[32], l2g[32], l2b[32];
};
__device__ WBlob g_wp;

// ---------------- prep: fold T=1 attention, pack mma fragments ----------------
__global__ void prep_kernel(
    const float* __restrict__ w1,  const float* __restrict__ b1,
    const float* __restrict__ wv1, const float* __restrict__ bv1, const float* __restrict__ g1,
    const float* __restrict__ l1g, const float* __restrict__ l1b,
    const float* __restrict__ w2,  const float* __restrict__ b2,
    const float* __restrict__ wv2, const float* __restrict__ bv2, const float* __restrict__ g2,
    const float* __restrict__ l2g, const float* __restrict__ l2b,
    const float* __restrict__ wo,  const float* __restrict__ bo)
{
    __shared__ float Af[64 * 32];
    __shared__ float Cf[32 * 32];
    const int t = threadIdx.x;
    const float g1v = g1[0], g2v = g2[0];

    // softmax over T=1 is identity: Af = w1 @ (I + g1*wv1), Cf = w2 @ (I + g2*wv2)
    for (int idx = t; idx < 64 * 32; idx += blockDim.x) {
        int i = idx >> 5, j = idx & 31;
        float s = 0.f;
        for (int m = 0; m < 32; m++) s += w1[i * 32 + m] * wv1[m * 32 + j];
        Af[idx] = w1[i * 32 + j] + g1v * s;
    }
    for (int idx = t; idx < 32 * 32; idx += blockDim.x) {
        int i = idx >> 5, j = idx & 31;
        float s = 0.f;
        for (int m = 0; m < 32; m++) s += w2[i * 32 + m] * wv2[m * 32 + j];
        Cf[idx] = w2[i * 32 + j] + g2v * s;
    }
    __syncthreads();

    // frag writer: value(k,n) from W[k*N + n]; b0 k=2t..+1, b1 k=2t+8..+9, n=8nn+g
    // GEMM1 frags from Af (N=32)
    for (int idx = t; idx < 4 * 4 * 32; idx += blockDim.x) {
        int kk = idx >> 7, nn = (idx >> 5) & 3, ln = idx & 31;
        int gg = ln >> 2, tt = ln & 3;
        int k0 = 16 * kk + 2 * tt, n = 8 * nn + gg;
        float a0 = Af[k0 * 32 + n],       a1 = Af[(k0 + 1) * 32 + n];
        float a2 = Af[(k0 + 8) * 32 + n], a3 = Af[(k0 + 9) * 32 + n];
        uint4 v;
        v.x = pkbf(a0, a1); v.y = pkbf(a2, a3);
        v.z = pkbf(a0 - bflo(v.x), a1 - bfhi(v.x));
        v.w = pkbf(a2 - bflo(v.y), a3 - bfhi(v.y));
        g_wp.w1[kk][nn][ln] = v;
    }
    // GEMM2 frags from Cf (N=32)
    for (int idx = t; idx < 2 * 4 * 32; idx += blockDim.x) {
        int kk = idx >> 7, nn = (idx >> 5) & 3, ln = idx & 31;
        int gg = ln >> 2, tt = ln & 3;
        int k0 = 16 * kk + 2 * tt, n = 8 * nn + gg;
        float a0 = Cf[k0 * 32 + n],       a1 = Cf[(k0 + 1) * 32 + n];
        float a2 = Cf[(k0 + 8) * 32 + n], a3 = Cf[(k0 + 9) * 32 + n];
        uint4 v;
        v.x = pkbf(a0, a1); v.y = pkbf(a2, a3);
        v.z = pkbf(a0 - bflo(v.x), a1 - bfhi(v.x));
        v.w = pkbf(a2 - bflo(v.y), a3 - bfhi(v.y));
        g_wp.w2[kk][nn][ln] = v;
    }
    // GEMM3 frags from wo [32,64] (N=64)
    for (int idx = t; idx < 2 * 8 * 32; idx += blockDim.x) {
        int kk = idx >> 8, nn = (idx >> 5) & 7, ln = idx & 31;
        int gg = ln >> 2, tt = ln & 3;
        int k0 = 16 * kk + 2 * tt, n = 8 * nn + gg;
        float a0 = wo[k0 * 64 + n],       a1 = wo[(k0 + 1) * 64 + n];
        float a2 = wo[(k0 + 8) * 64 + n], a3 = wo[(k0 + 9) * 64 + n];
        uint4 v;
        v.x = pkbf(a0, a1); v.y = pkbf(a2, a3);
        v.z = pkbf(a0 - bflo(v.x), a1 - bfhi(v.x));
        v.w = pkbf(a2 - bflo(v.y), a3 - bfhi(v.y));
        g_wp.w3[kk][nn][ln] = v;
    }
    if (t < 32) {
        int j = t;
        float s1 = 0.f, s2 = 0.f;
        for (int m = 0; m < 32; m++) {
            s1 += b1[m] * wv1[m * 32 + j];
            s2 += b2[m] * wv2[m * 32 + j];
        }
        g_wp.ab[j] = b1[j] + g1v * (s1 + bv1[j]);
        g_wp.cb[j] = b2[j] + g2v * (s2 + bv2[j]);
        g_wp.l1g[j] = l1g[j]; g_wp.l1b[j] = l1b[j];
        g_wp.l2g[j] = l2g[j]; g_wp.l2b[j] = l2b[j];
    }
    if (t < 64) g_wp.bo[t] = bo[t];
}

// bias + LN + leaky on a [16 x 32] accumulator block; emit next-stage A frags.
// acc[nn][0..3]: (row g, col 8nn+2t), (g, +1), (g+8, 8nn+2t), (g+8, +1)
__device__ __forceinline__ void ln_block(float acc[4][4],
                                         const float* __restrict__ bias,
                                         const float* __restrict__ gg,
                                         const float* __restrict__ bb,
                                         int t, u32 oh[2][4], u32 ol[2][4])
{
    float s0 = 0.f, q0 = 0.f, s1 = 0.f, q1 = 0.f;
#pragma unroll
    for (int nn = 0; nn < 4; nn++) {
        float2 bv = *(const float2*)(bias + 8 * nn + 2 * t);
        acc[nn][0] += bv.x; acc[nn][1] += bv.y;
        acc[nn][2] += bv.x; acc[nn][3] += bv.y;
        s0 += acc[nn][0] + acc[nn][1];
        q0 += acc[nn][0] * acc[nn][0] + acc[nn][1] * acc[nn][1];
        s1 += acc[nn][2] + acc[nn][3];
        q1 += acc[nn][2] * acc[nn][2] + acc[nn][3] * acc[nn][3];
    }
#pragma unroll
    for (int m = 1; m < 4; m <<= 1) {
        s0 += __shfl_xor_sync(0xffffffffu, s0, m, 4);
        q0 += __shfl_xor_sync(0xffffffffu, q0, m, 4);
        s1 += __shfl_xor_sync(0xffffffffu, s1, m, 4);
        q1 += __shfl_xor_sync(0xffffffffu, q1, m, 4);
    }
    const float c = 1.0f / 32.0f;
    const float m0 = s0 * c, r0 = rsqrtf(fmaf(-m0, m0, q0 * c) + 1e-5f);
    const float m1 = s1 * c, r1 = rsqrtf(fmaf(-m1, m1, q1 * c) + 1e-5f);

    float y[4][4];
#pragma unroll
    for (int nn = 0; nn < 4; nn++) {
        float2 gv = *(const float2*)(gg + 8 * nn + 2 * t);
        float2 bv = *(const float2*)(bb + 8 * nn + 2 * t);
        float u;
        u = fmaf((acc[nn][0] - m0) * r0, gv.x, bv.x); y[nn][0] = fmaxf(u, 0.01f * u);
        u = fmaf((acc[nn][1] - m0) * r0, gv.y, bv.y); y[nn][1] = fmaxf(u, 0.01f * u);
        u = fmaf((acc[nn][2] - m1) * r1, gv.x, bv.x); y[nn][2] = fmaxf(u, 0.01f * u);
        u = fmaf((acc[nn][3] - m1) * r1, gv.y, bv.y); y[nn][3] = fmaxf(u, 0.01f * u);
    }
    // D-layout == A-layout: kfrag kk <- nfrags {2kk, 2kk+1}
#pragma unroll
    for (int kk = 0; kk < 2; kk++) {
        split2(y[2 * kk][0],     y[2 * kk][1],     oh[kk][0], ol[kk][0]);
        split2(y[2 * kk][2],     y[2 * kk][3],     oh[kk][1], ol[kk][1]);
        split2(y[2 * kk + 1][0], y[2 * kk + 1][1], oh[kk][2], ol[kk][2]);
        split2(y[2 * kk + 1][2], y[2 * kk + 1][3], oh[kk][3], ol[kk][3]);
    }
}

// ---------------- fused kernel: one warp per 16-row tile, no smem activations ----------------
__global__ void __launch_bounds__(256, 2)
fused_kernel(const float* __restrict__ x, float* __restrict__ out, int nrows, int ntiles)
{
    __shared__ WBlob sw;
    {
        const uint4* s = reinterpret_cast<const uint4*>(&g_wp);
        uint4* d = reinterpret_cast<uint4*>(&sw);
        for (int i = threadIdx.x; i < (int)(sizeof(WBlob) / 16); i += 256) d[i] = s[i];
    }
    __syncthreads();

    const int wid  = threadIdx.x >> 5;
    const int lane = threadIdx.x & 31;
    const int g = lane >> 2, t = lane & 3;

    for (int tile = blockIdx.x * 8 + wid; tile < ntiles; tile += gridDim.x * 8) {
        const int row0 = tile * 16 + g;
        const int row1 = row0 + 8;
        const bool v0 = row0 < nrows, v1 = row1 < nrows;
        const float* p0 = x + (size_t)row0 * 64 + 2 * t;
        const float* p1 = x + (size_t)row1 * 64 + 2 * t;

        // ---- load x, hi/lo split into A frags ----
        u32 ah[4][4], al[4][4];
#pragma unroll
        for (int kk = 0; kk < 4; kk++) {
            float2 x00 = v0 ? *(const float2*)(p0 + 16 * kk)     : make_float2(0.f, 0.f);
            float2 x10 = v1 ? *(const float2*)(p1 + 16 * kk)     : make_float2(0.f, 0.f);
            float2 x01 = v0 ? *(const float2*)(p0 + 16 * kk + 8) : make_float2(0.f, 0.f);
            float2 x11 = v1 ? *(const float2*)(p1 + 16 * kk + 8) : make_float2(0.f, 0.f);
            split2(x00.x, x00.y, ah[kk][0], al[kk][0]);
            split2(x10.x, x10.y, ah[kk][1], al[kk][1]);
            split2(x01.x, x01.y, ah[kk][2], al[kk][2]);
            split2(x11.x, x11.y, ah[kk][3], al[kk][3]);
        }

        // ---- GEMM1: [16x64] @ [64x32], 3-term split ----
        float acc[4][4];
#pragma unroll
        for (int nn = 0; nn < 4; nn++) {
            acc[nn][0] = acc[nn][1] = acc[nn][2] = acc[nn][3] = 0.f;
#pragma unroll
            for (int kk = 0; kk < 4; kk++) {
                uint4 w = sw.w1[kk][nn][lane];
                MMA(acc[nn], ah[kk][0], ah[kk][1], ah[kk][2], ah[kk][3], w.x, w.y);
                MMA(acc[nn], al[kk][0], al[kk][1], al[kk][2], al[kk][3], w.x, w.y);
                MMA(acc[nn], ah[kk][0], ah[kk][1], ah[kk][2], ah[kk][3], w.z, w.w);
            }
        }

        // ---- bias + LN1 + leaky -> A2 ----
        u32 a2h[2][4], a2l[2][4];
        ln_block(acc, sw.ab, sw.l1g, sw.l1b, t, a2h, a2l);

        // ---- GEMM2: [16x32] @ [32x32] ----
        float acc2[4][4];
#pragma unroll
        for (int nn = 0; nn < 4; nn++) {
            acc2[nn][0] = acc2[nn][1] = acc2[nn][2] = acc2[nn][3] = 0.f;
#pragma unroll
            for (int kk = 0; kk < 2; kk++) {
                uint4 w = sw.w2[kk][nn][lane];
                MMA(acc2[nn], a2h[kk][0], a2h[kk][1], a2h[kk][2], a2h[kk][3], w.x, w.y);
                MMA(acc2[nn], a2l[kk][0], a2l[kk][1], a2l[kk][2], a2l[kk][3], w.x, w.y);
                MMA(acc2[nn], a2h[kk][0], a2h[kk][1], a2h[kk][2], a2h[kk][3], w.z, w.w);
            }
        }

        // ---- bias + LN2 + leaky -> A3 ----
        u32 a3h[2][4], a3l[2][4];
        ln_block(acc2, sw.cb, sw.l2g, sw.l2b, t, a3h, a3l);

        // ---- GEMM3: [16x32] @ [32x64] ----
        float acc3[8][4];
#pragma unroll
        for (int nn = 0; nn < 8; nn++) {
            acc3[nn][0] = acc3[nn][1] = acc3[nn][2] = acc3[nn][3] = 0.f;
#pragma unroll
            for (int kk = 0; kk < 2; kk++) {
                uint4 w = sw.w3[kk][nn][lane];
                MMA(acc3[nn], a3h[kk][0], a3h[kk][1], a3h[kk][2], a3h[kk][3], w.x, w.y);
                MMA(acc3[nn], a3l[kk][0], a3l[kk][1], a3l[kk][2], a3l[kk][3], w.x, w.y);
                MMA(acc3[nn], a3h[kk][0], a3h[kk][1], a3h[kk][2], a3h[kk][3], w.z, w.w);
            }
        }

        // ---- + bo, store ----
        float* o0 = out + (size_t)row0 * 64 + 2 * t;
        float* o1 = out + (size_t)row1 * 64 + 2 * t;
#pragma unroll
        for (int nn = 0; nn < 8; nn++) {
            float2 b = *(const float2*)(sw.bo + 8 * nn + 2 * t);
            if (v0) {
                float2 o; o.x = acc3[nn][0] + b.x; o.y = acc3[nn][1] + b.y;
                *(float2*)(o0 + 8 * nn) = o;
            }
            if (v1) {
                float2 o; o.x = acc3[nn][2] + b.x; o.y = acc3[nn][3] + b.y;
                *(float2*)(o1 + 8 * nn) = o;
            }
        }
    }
}

extern "C" void kernel_launch(void* const* d_in, const int* in_sizes, int n_in,
                              void* d_out, int out_size)
{
    const float* x   = (const float*)d_in[0];
    const float* w1  = (const float*)d_in[1];
    const float* b1  = (const float*)d_in[2];
    const float* wv1 = (const float*)d_in[7];
    const float* bv1 = (const float*)d_in[8];
    const float* g1  = (const float*)d_in[9];
    const float* l1g = (const float*)d_in[10];
    const float* l1b = (const float*)d_in[11];
    const float* w2  = (const float*)d_in[12];
    const float* b2  = (const float*)d_in[13];
    const float* wv2 = (const float*)d_in[18];
    const float* bv2 = (const float*)d_in[19];
    const float* g2  = (const float*)d_in[20];
    const float* l2g = (const float*)d_in[21];
    const float* l2b = (const float*)d_in[22];
    const float* wo  = (const float*)d_in[23];
    const float* bo  = (const float*)d_in[24];

    const int B = in_sizes[0] / 64;
    const int ntiles = (B + 15) / 16;

    prep_kernel<<<1, 256>>>(w1, b1, wv1, bv1, g1, l1g, l1b,
                            w2, b2, wv2, bv2, g2, l2g, l2b, wo, bo);

    int grid = 2 * 148;                       // 2 CTAs/SM x 8 warps, persistent
    if (grid > (ntiles + 7) / 8) grid = (ntiles + 7) / 8;
    fused_kernel<<<grid, 256>>>(x, (float*)d_out, B, ntiles);
}

// round 5
// speedup vs baseline: 3.4126x; 1.1583x over previous
#include <cuda_runtime.h>
#include <cstdint>

typedef uint32_t u32;

__device__ __forceinline__ u32 pkbf(float lo, float hi) {
    u32 r; asm("cvt.rn.bf16x2.f32 %0, %1, %2;" : "=r"(r) : "f"(hi), "f"(lo)); return r;
}
__device__ __forceinline__ float bflo(u32 h) { return __uint_as_float(h << 16); }
__device__ __forceinline__ float bfhi(u32 h) { return __uint_as_float(h & 0xFFFF0000u); }
__device__ __forceinline__ void split2(float a, float b, u32& hp, u32& lp) {
    hp = pkbf(a, b);
    lp = pkbf(a - bflo(hp), b - bfhi(hp));
}

#define MMA(d, a0, a1, a2, a3, b0, b1)                                      \
    asm volatile("mma.sync.aligned.m16n8k16.row.col.f32.bf16.bf16.f32 "     \
                 "{%0,%1,%2,%3},{%4,%5,%6,%7},{%8,%9},{%0,%1,%2,%3};"       \
                 : "+f"((d)[0]), "+f"((d)[1]), "+f"((d)[2]), "+f"((d)[3])   \
                 : "r"(a0), "r"(a1), "r"(a2), "r"(a3), "r"(b0), "r"(b1))

// Per-lane weight fragments: uint4 = {hi_b0, hi_b1, lo_b0, lo_b1}
struct __align__(16) WBlob {
    uint4 w1[4][4][32];   // GEMM1, K-permuted for coalesced x loads
    uint4 w2[2][4][32];   // GEMM2, identity layout
    uint4 w3[2][8][32];   // GEMM3, N-permuted for coalesced out stores
    float ab[32], cb[32], bo[64];       // bo is column-permuted like w3
    float l1g[32], l1b[32], l2g[32], l2b[32];
};
__device__ WBlob g_wp;

// ---------------- prep ----------------
__global__ void prep_kernel(
    const float* __restrict__ w1,  const float* __restrict__ b1,
    const float* __restrict__ wv1, const float* __restrict__ bv1, const float* __restrict__ g1,
    const float* __restrict__ l1g, const float* __restrict__ l1b,
    const float* __restrict__ w2,  const float* __restrict__ b2,
    const float* __restrict__ wv2, const float* __restrict__ bv2, const float* __restrict__ g2,
    const float* __restrict__ l2g, const float* __restrict__ l2b,
    const float* __restrict__ wo,  const float* __restrict__ bo)
{
    __shared__ float Af[64 * 32];
    __shared__ float Cf[32 * 32];
    const int t = threadIdx.x;
    const float g1v = g1[0], g2v = g2[0];

    // fold T=1 attention (softmax == 1)
    for (int idx = t; idx < 64 * 32; idx += blockDim.x) {
        int i = idx >> 5, j = idx & 31;
        float s = 0.f;
        for (int m = 0; m < 32; m++) s += w1[i * 32 + m] * wv1[m * 32 + j];
        Af[idx] = w1[i * 32 + j] + g1v * s;
    }
    for (int idx = t; idx < 32 * 32; idx += blockDim.x) {
        int i = idx >> 5, j = idx & 31;
        float s = 0.f;
        for (int m = 0; m < 32; m++) s += w2[i * 32 + m] * wv2[m * 32 + j];
        Cf[idx] = w2[i * 32 + j] + g2v * s;
    }
    __syncthreads();

    // GEMM1 frags: K-permuted. phys(2t,2t+1)->logical 16kk+4t+(0,1); phys(2t+8,+9)->16kk+4t+(2,3)
    for (int idx = t; idx < 4 * 4 * 32; idx += blockDim.x) {
        int kk = idx >> 7, nn = (idx >> 5) & 3, ln = idx & 31;
        int gg = ln >> 2, tt = ln & 3;
        int kb = 16 * kk + 4 * tt, n = 8 * nn + gg;
        float a0 = Af[kb * 32 + n],       a1 = Af[(kb + 1) * 32 + n];
        float a2 = Af[(kb + 2) * 32 + n], a3 = Af[(kb + 3) * 32 + n];
        uint4 v;
        v.x = pkbf(a0, a1); v.y = pkbf(a2, a3);
        v.z = pkbf(a0 - bflo(v.x), a1 - bfhi(v.x));
        v.w = pkbf(a2 - bflo(v.y), a3 - bfhi(v.y));
        g_wp.w1[kk][nn][ln] = v;
    }
    // GEMM2 frags: identity layout (D-frag == A-frag chaining)
    for (int idx = t; idx < 2 * 4 * 32; idx += blockDim.x) {
        int kk = idx >> 7, nn = (idx >> 5) & 3, ln = idx & 31;
        int gg = ln >> 2, tt = ln & 3;
        int k0 = 16 * kk + 2 * tt, n = 8 * nn + gg;
        float a0 = Cf[k0 * 32 + n],       a1 = Cf[(k0 + 1) * 32 + n];
        float a2 = Cf[(k0 + 8) * 32 + n], a3 = Cf[(k0 + 9) * 32 + n];
        uint4 v;
        v.x = pkbf(a0, a1); v.y = pkbf(a2, a3);
        v.z = pkbf(a0 - bflo(v.x), a1 - bfhi(v.x));
        v.w = pkbf(a2 - bflo(v.y), a3 - bfhi(v.y));
        g_wp.w2[kk][nn][ln] = v;
    }
    // GEMM3 frags: output-column permuted: phys col gg of ntile nn -> logical 16*(gg>>1)+2nn+(gg&1)
    for (int idx = t; idx < 2 * 8 * 32; idx += blockDim.x) {
        int kk = idx >> 8, nn = (idx >> 5) & 7, ln = idx & 31;
        int gg = ln >> 2, tt = ln & 3;
        int k0 = 16 * kk + 2 * tt;
        int c = 16 * (gg >> 1) + 2 * nn + (gg & 1);
        float a0 = wo[k0 * 64 + c],       a1 = wo[(k0 + 1) * 64 + c];
        float a2 = wo[(k0 + 8) * 64 + c], a3 = wo[(k0 + 9) * 64 + c];
        uint4 v;
        v.x = pkbf(a0, a1); v.y = pkbf(a2, a3);
        v.z = pkbf(a0 - bflo(v.x), a1 - bfhi(v.x));
        v.w = pkbf(a2 - bflo(v.y), a3 - bfhi(v.y));
        g_wp.w3[kk][nn][ln] = v;
    }
    if (t < 32) {
        int j = t;
        float s1 = 0.f, s2 = 0.f;
        for (int m = 0; m < 32; m++) {
            s1 += b1[m] * wv1[m * 32 + j];
            s2 += b2[m] * wv2[m * 32 + j];
        }
        g_wp.ab[j] = b1[j] + g1v * (s1 + bv1[j]);
        g_wp.cb[j] = b2[j] + g2v * (s2 + bv2[j]);
        g_wp.l1g[j] = l1g[j]; g_wp.l1b[j] = l1b[j];
        g_wp.l2g[j] = l2g[j]; g_wp.l2b[j] = l2b[j];
    }
    if (t < 64) g_wp.bo[t] = bo[t];   // bo stored in LOGICAL order; kernel reads permuted slices
}

// bias + LN + leaky on [16 x 32] block; emit next-stage A frags (identity channel map)
__device__ __forceinline__ void ln_block(float acc[4][4],
                                         const float* __restrict__ bias,
                                         const float* __restrict__ gg,
                                         const float* __restrict__ bb,
                                         int t, u32 oh[2][4], u32 ol[2][4])
{
    float s0 = 0.f, q0 = 0.f, s1 = 0.f, q1 = 0.f;
#pragma unroll
    for (int nn = 0; nn < 4; nn++) {
        float2 bv = *(const float2*)(bias + 8 * nn + 2 * t);
        acc[nn][0] += bv.x; acc[nn][1] += bv.y;
        acc[nn][2] += bv.x; acc[nn][3] += bv.y;
        s0 += acc[nn][0] + acc[nn][1];
        q0 += acc[nn][0] * acc[nn][0] + acc[nn][1] * acc[nn][1];
        s1 += acc[nn][2] + acc[nn][3];
        q1 += acc[nn][2] * acc[nn][2] + acc[nn][3] * acc[nn][3];
    }
#pragma unroll
    for (int m = 1; m < 4; m <<= 1) {
        s0 += __shfl_xor_sync(0xffffffffu, s0, m, 4);
        q0 += __shfl_xor_sync(0xffffffffu, q0, m, 4);
        s1 += __shfl_xor_sync(0xffffffffu, s1, m, 4);
        q1 += __shfl_xor_sync(0xffffffffu, q1, m, 4);
    }
    const float c = 1.0f / 32.0f;
    const float m0 = s0 * c, r0 = rsqrtf(fmaf(-m0, m0, q0 * c) + 1e-5f);
    const float m1 = s1 * c, r1 = rsqrtf(fmaf(-m1, m1, q1 * c) + 1e-5f);

    float y[4][4];
#pragma unroll
    for (int nn = 0; nn < 4; nn++) {
        float2 gv = *(const float2*)(gg + 8 * nn + 2 * t);
        float2 bv = *(const float2*)(bb + 8 * nn + 2 * t);
        float u;
        u = fmaf((acc[nn][0] - m0) * r0, gv.x, bv.x); y[nn][0] = fmaxf(u, 0.01f * u);
        u = fmaf((acc[nn][1] - m0) * r0, gv.y, bv.y); y[nn][1] = fmaxf(u, 0.01f * u);
        u = fmaf((acc[nn][2] - m1) * r1, gv.x, bv.x); y[nn][2] = fmaxf(u, 0.01f * u);
        u = fmaf((acc[nn][3] - m1) * r1, gv.y, bv.y); y[nn][3] = fmaxf(u, 0.01f * u);
    }
#pragma unroll
    for (int kk = 0; kk < 2; kk++) {
        split2(y[2 * kk][0],     y[2 * kk][1],     oh[kk][0], ol[kk][0]);
        split2(y[2 * kk][2],     y[2 * kk][3],     oh[kk][1], ol[kk][1]);
        split2(y[2 * kk + 1][0], y[2 * kk + 1][1], oh[kk][2], ol[kk][2]);
        split2(y[2 * kk + 1][2], y[2 * kk + 1][3], oh[kk][3], ol[kk][3]);
    }
}

__device__ __forceinline__ void loadx(const float* __restrict__ x, int tile, int g, int t,
                                      int nrows, float4 xa[4], float4 xb[4])
{
    const int r0 = tile * 16 + g, r1 = r0 + 8;
    const float* b0 = x + (size_t)r0 * 64 + 4 * t;
    const float* b1 = x + (size_t)r1 * 64 + 4 * t;
    const bool v0 = r0 < nrows, v1 = r1 < nrows;
#pragma unroll
    for (int kk = 0; kk < 4; kk++) {
        xa[kk] = v0 ? __ldcs((const float4*)(b0 + 16 * kk)) : make_float4(0.f, 0.f, 0.f, 0.f);
        xb[kk] = v1 ? __ldcs((const float4*)(b1 + 16 * kk)) : make_float4(0.f, 0.f, 0.f, 0.f);
    }
}

// ---------------- fused kernel: 1 warp per 16-row tile, weights in regs/smem ----------------
__global__ void __launch_bounds__(128, 2)
fused_kernel(const float* __restrict__ x, float* __restrict__ out, int nrows, int ntiles)
{
    __shared__ uint4 w1s[512];            // GEMM1 frags
    __shared__ float sp[192];             // ab | l1g | l1b | cb | l2g | l2b
    const int tid = threadIdx.x;
    {
        const uint4* s = (const uint4*)g_wp.w1;
        for (int i = tid; i < 512; i += 128) w1s[i] = s[i];
        if (tid < 32) {
            sp[tid]       = g_wp.ab[tid];
            sp[32 + tid]  = g_wp.l1g[tid];
            sp[64 + tid]  = g_wp.l1b[tid];
            sp[96 + tid]  = g_wp.cb[tid];
            sp[128 + tid] = g_wp.l2g[tid];
            sp[160 + tid] = g_wp.l2b[tid];
        }
    }
    const int wid = tid >> 5, lane = tid & 31;
    const int g = lane >> 2, t = lane & 3;

    // persistent register weights
    uint4 w2r[2][4], w3r[2][8];
#pragma unroll
    for (int kk = 0; kk < 2; kk++)
#pragma unroll
        for (int nn = 0; nn < 4; nn++) w2r[kk][nn] = g_wp.w2[kk][nn][lane];
#pragma unroll
    for (int kk = 0; kk < 2; kk++)
#pragma unroll
        for (int nn = 0; nn < 8; nn++) w3r[kk][nn] = g_wp.w3[kk][nn][lane];
    float4 bor[4];
#pragma unroll
    for (int j = 0; j < 4; j++) bor[j] = *(const float4*)(g_wp.bo + 16 * t + 4 * j);
    __syncthreads();

    const int stride = gridDim.x * 4;
    int tile = blockIdx.x * 4 + wid;
    if (tile >= ntiles) return;

    float4 xa[4], xb[4];
    loadx(x, tile, g, t, nrows, xa, xb);

    for (; tile < ntiles; tile += stride) {
        // ---- convert current x to hi/lo A frags ----
        u32 ah[4][4], al[4][4];
#pragma unroll
        for (int kk = 0; kk < 4; kk++) {
            split2(xa[kk].x, xa[kk].y, ah[kk][0], al[kk][0]);
            split2(xb[kk].x, xb[kk].y, ah[kk][1], al[kk][1]);
            split2(xa[kk].z, xa[kk].w, ah[kk][2], al[kk][2]);
            split2(xb[kk].z, xb[kk].w, ah[kk][3], al[kk][3]);
        }
        // ---- prefetch next tile (xa consumed above; WAR safe) ----
        if (tile + stride < ntiles) loadx(x, tile + stride, g, t, nrows, xa, xb);

        // ---- GEMM1: [16x64]@[64x32], weights from smem ----
        float acc[4][4];
#pragma unroll
        for (int nn = 0; nn < 4; nn++) {
            acc[nn][0] = acc[nn][1] = acc[nn][2] = acc[nn][3] = 0.f;
#pragma unroll
            for (int kk = 0; kk < 4; kk++) {
                uint4 w = w1s[(kk * 4 + nn) * 32 + lane];
                MMA(acc[nn], ah[kk][0], ah[kk][1], ah[kk][2], ah[kk][3], w.x, w.y);
                MMA(acc[nn], al[kk][0], al[kk][1], al[kk][2], al[kk][3], w.x, w.y);
                MMA(acc[nn], ah[kk][0], ah[kk][1], ah[kk][2], ah[kk][3], w.z, w.w);
            }
        }

        u32 a2h[2][4], a2l[2][4];
        ln_block(acc, sp + 0, sp + 32, sp + 64, t, a2h, a2l);

        // ---- GEMM2: [16x32]@[32x32], weights in regs ----
        float acc2[4][4];
#pragma unroll
        for (int nn = 0; nn < 4; nn++) {
            acc2[nn][0] = acc2[nn][1] = acc2[nn][2] = acc2[nn][3] = 0.f;
#pragma unroll
            for (int kk = 0; kk < 2; kk++) {
                uint4 w = w2r[kk][nn];
                MMA(acc2[nn], a2h[kk][0], a2h[kk][1], a2h[kk][2], a2h[kk][3], w.x, w.y);
                MMA(acc2[nn], a2l[kk][0], a2l[kk][1], a2l[kk][2], a2l[kk][3], w.x, w.y);
                MMA(acc2[nn], a2h[kk][0], a2h[kk][1], a2h[kk][2], a2h[kk][3], w.z, w.w);
            }
        }

        u32 a3h[2][4], a3l[2][4];
        ln_block(acc2, sp + 96, sp + 128, sp + 160, t, a3h, a3l);

        // ---- GEMM3: [16x32]@[32x64], weights in regs, output cols permuted ----
        float acc3[8][4];
#pragma unroll
        for (int nn = 0; nn < 8; nn++) {
            acc3[nn][0] = acc3[nn][1] = acc3[nn][2] = acc3[nn][3] = 0.f;
#pragma unroll
            for (int kk = 0; kk < 2; kk++) {
                uint4 w = w3r[kk][nn];
                MMA(acc3[nn], a3h[kk][0], a3h[kk][1], a3h[kk][2], a3h[kk][3], w.x, w.y);
                MMA(acc3[nn], a3l[kk][0], a3l[kk][1], a3l[kk][2], a3l[kk][3], w.x, w.y);
                MMA(acc3[nn], a3h[kk][0], a3h[kk][1], a3h[kk][2], a3h[kk][3], w.z, w.w);
            }
        }

        // ---- + bo, coalesced float4 stores: lane t owns logical cols [16t..16t+15] ----
        const int r0 = tile * 16 + g, r1 = r0 + 8;
        if (r0 < nrows) {
            float* o = out + (size_t)r0 * 64 + 16 * t;
#pragma unroll
            for (int j = 0; j < 4; j++) {
                float4 v;
                v.x = acc3[2 * j][0]     + bor[j].x;
                v.y = acc3[2 * j][1]     + bor[j].y;
                v.z = acc3[2 * j + 1][0] + bor[j].z;
                v.w = acc3[2 * j + 1][1] + bor[j].w;
                __stcs((float4*)(o + 4 * j), v);
            }
        }
        if (r1 < nrows) {
            float* o = out + (size_t)r1 * 64 + 16 * t;
#pragma unroll
            for (int j = 0; j < 4; j++) {
                float4 v;
                v.x = acc3[2 * j][2]     + bor[j].x;
                v.y = acc3[2 * j][3]     + bor[j].y;
                v.z = acc3[2 * j + 1][2] + bor[j].z;
                v.w = acc3[2 * j + 1][3] + bor[j].w;
                __stcs((float4*)(o + 4 * j), v);
            }
        }
    }
}

extern "C" void kernel_launch(void* const* d_in, const int* in_sizes, int n_in,
                              void* d_out, int out_size)
{
    const float* x   = (const float*)d_in[0];
    const float* w1  = (const float*)d_in[1];
    const float* b1  = (const float*)d_in[2];
    const float* wv1 = (const float*)d_in[7];
    const float* bv1 = (const float*)d_in[8];
    const float* g1  = (const float*)d_in[9];
    const float* l1g = (const float*)d_in[10];
    const float* l1b = (const float*)d_in[11];
    const float* w2  = (const float*)d_in[12];
    const float* b2  = (const float*)d_in[13];
    const float* wv2 = (const float*)d_in[18];
    const float* bv2 = (const float*)d_in[19];
    const float* g2  = (const float*)d_in[20];
    const float* l2g = (const float*)d_in[21];
    const float* l2b = (const float*)d_in[22];
    const float* wo  = (const float*)d_in[23];
    const float* bo  = (const float*)d_in[24];

    const int B = in_sizes[0] / 64;
    const int ntiles = (B + 15) / 16;

    prep_kernel<<<1, 256>>>(w1, b1, wv1, bv1, g1, l1g, l1b,
                            w2, b2, wv2, bv2, g2, l2g, l2b, wo, bo);

    int grid = 2 * 148;                       // 2 CTAs/SM x 4 warps, persistent
    int need = (ntiles + 3) / 4;
    if (grid > need) grid = need;
    fused_kernel<<<grid, 128>>>(x, (float*)d_out, B, ntiles);
}

// round 6
// speedup vs baseline: 3.9433x; 1.1555x over previous
#include <cuda_runtime.h>
#include <cstdint>

typedef uint32_t u32;

__device__ __forceinline__ u32 pkbf(float lo, float hi) {
    u32 r; asm("cvt.rn.bf16x2.f32 %0, %1, %2;" : "=r"(r) : "f"(hi), "f"(lo)); return r;
}
__device__ __forceinline__ float bflo(u32 h) { return __uint_as_float(h << 16); }
__device__ __forceinline__ float bfhi(u32 h) { return __uint_as_float(h & 0xFFFF0000u); }
__device__ __forceinline__ void split2(float a, float b, u32& hp, u32& lp) {
    hp = pkbf(a, b);
    lp = pkbf(a - bflo(hp), b - bfhi(hp));
}

#define MMA(d, a0, a1, a2, a3, b0, b1)                                      \
    asm volatile("mma.sync.aligned.m16n8k16.row.col.f32.bf16.bf16.f32 "     \
                 "{%0,%1,%2,%3},{%4,%5,%6,%7},{%8,%9},{%0,%1,%2,%3};"       \
                 : "+f"((d)[0]), "+f"((d)[1]), "+f"((d)[2]), "+f"((d)[3])   \
                 : "r"(a0), "r"(a1), "r"(a2), "r"(a3), "r"(b0), "r"(b1))

// Per-lane weight fragments: uint4 = {hi_b0, hi_b1, lo_b0, lo_b1}
struct __align__(16) WBlob {
    uint4 w1[4][4][32];   // GEMM1, K-permuted for coalesced x loads
    uint4 w2[2][4][32];   // GEMM2, identity layout
    uint4 w3[2][8][32];   // GEMM3, N-permuted so store j of lane t is float4 @ col 16j+4t
    float ab[32], cb[32], bo[64];       // bo in LOGICAL column order
    float l1g[32], l1b[32], l2g[32], l2b[32];
};
__device__ WBlob g_wp;

// ---------------- prep ----------------
__global__ void prep_kernel(
    const float* __restrict__ w1,  const float* __restrict__ b1,
    const float* __restrict__ wv1, const float* __restrict__ bv1, const float* __restrict__ g1,
    const float* __restrict__ l1g, const float* __restrict__ l1b,
    const float* __restrict__ w2,  const float* __restrict__ b2,
    const float* __restrict__ wv2, const float* __restrict__ bv2, const float* __restrict__ g2,
    const float* __restrict__ l2g, const float* __restrict__ l2b,
    const float* __restrict__ wo,  const float* __restrict__ bo)
{
    __shared__ float Af[64 * 32];
    __shared__ float Cf[32 * 32];
    const int t = threadIdx.x;
    const float g1v = g1[0], g2v = g2[0];

    // fold T=1 attention (softmax == 1)
    for (int idx = t; idx < 64 * 32; idx += blockDim.x) {
        int i = idx >> 5, j = idx & 31;
        float s = 0.f;
        for (int m = 0; m < 32; m++) s += w1[i * 32 + m] * wv1[m * 32 + j];
        Af[idx] = w1[i * 32 + j] + g1v * s;
    }
    for (int idx = t; idx < 32 * 32; idx += blockDim.x) {
        int i = idx >> 5, j = idx & 31;
        float s = 0.f;
        for (int m = 0; m < 32; m++) s += w2[i * 32 + m] * wv2[m * 32 + j];
        Cf[idx] = w2[i * 32 + j] + g2v * s;
    }
    __syncthreads();

    // GEMM1 frags: K-permuted so each lane's A frag is one contiguous float4 of x
    for (int idx = t; idx < 4 * 4 * 32; idx += blockDim.x) {
        int kk = idx >> 7, nn = (idx >> 5) & 3, ln = idx & 31;
        int gg = ln >> 2, tt = ln & 3;
        int kb = 16 * kk + 4 * tt, n = 8 * nn + gg;
        float a0 = Af[kb * 32 + n],       a1 = Af[(kb + 1) * 32 + n];
        float a2 = Af[(kb + 2) * 32 + n], a3 = Af[(kb + 3) * 32 + n];
        uint4 v;
        v.x = pkbf(a0, a1); v.y = pkbf(a2, a3);
        v.z = pkbf(a0 - bflo(v.x), a1 - bfhi(v.x));
        v.w = pkbf(a2 - bflo(v.y), a3 - bfhi(v.y));
        g_wp.w1[kk][nn][ln] = v;
    }
    // GEMM2 frags: identity layout (D-frag == A-frag chaining)
    for (int idx = t; idx < 2 * 4 * 32; idx += blockDim.x) {
        int kk = idx >> 7, nn = (idx >> 5) & 3, ln = idx & 31;
        int gg = ln >> 2, tt = ln & 3;
        int k0 = 16 * kk + 2 * tt, n = 8 * nn + gg;
        float a0 = Cf[k0 * 32 + n],       a1 = Cf[(k0 + 1) * 32 + n];
        float a2 = Cf[(k0 + 8) * 32 + n], a3 = Cf[(k0 + 9) * 32 + n];
        uint4 v;
        v.x = pkbf(a0, a1); v.y = pkbf(a2, a3);
        v.z = pkbf(a0 - bflo(v.x), a1 - bfhi(v.x));
        v.w = pkbf(a2 - bflo(v.y), a3 - bfhi(v.y));
        g_wp.w2[kk][nn][ln] = v;
    }
    // GEMM3 frags: phys col gg of ntile nn -> logical 16*(nn>>1) + 4*(gg>>1) + 2*(nn&1) + (gg&1)
    // => at store time, lane t instr j writes logical cols [16j+4t .. 16j+4t+3] as one float4
    for (int idx = t; idx < 2 * 8 * 32; idx += blockDim.x) {
        int kk = idx >> 8, nn = (idx >> 5) & 7, ln = idx & 31;
        int gg = ln >> 2, tt = ln & 3;
        int k0 = 16 * kk + 2 * tt;
        int c = 16 * (nn >> 1) + 4 * (gg >> 1) + 2 * (nn & 1) + (gg & 1);
        float a0 = wo[k0 * 64 + c],       a1 = wo[(k0 + 1) * 64 + c];
        float a2 = wo[(k0 + 8) * 64 + c], a3 = wo[(k0 + 9) * 64 + c];
        uint4 v;
        v.x = pkbf(a0, a1); v.y = pkbf(a2, a3);
        v.z = pkbf(a0 - bflo(v.x), a1 - bfhi(v.x));
        v.w = pkbf(a2 - bflo(v.y), a3 - bfhi(v.y));
        g_wp.w3[kk][nn][ln] = v;
    }
    if (t < 32) {
        int j = t;
        float s1 = 0.f, s2 = 0.f;
        for (int m = 0; m < 32; m++) {
            s1 += b1[m] * wv1[m * 32 + j];
            s2 += b2[m] * wv2[m * 32 + j];
        }
        g_wp.ab[j] = b1[j] + g1v * (s1 + bv1[j]);
        g_wp.cb[j] = b2[j] + g2v * (s2 + bv2[j]);
        g_wp.l1g[j] = l1g[j]; g_wp.l1b[j] = l1b[j];
        g_wp.l2g[j] = l2g[j]; g_wp.l2b[j] = l2b[j];
    }
    if (t < 64) g_wp.bo[t] = bo[t];
}

// bias + LN + leaky on [16 x 32] block; emit next-stage A frags (identity channel map)
__device__ __forceinline__ void ln_block(float acc[4][4],
                                         const float* __restrict__ bias,
                                         const float* __restrict__ gg,
                                         const float* __restrict__ bb,
                                         int t, u32 oh[2][4], u32 ol[2][4])
{
    float s0 = 0.f, q0 = 0.f, s1 = 0.f, q1 = 0.f;
#pragma unroll
    for (int nn = 0; nn < 4; nn++) {
        float2 bv = *(const float2*)(bias + 8 * nn + 2 * t);
        acc[nn][0] += bv.x; acc[nn][1] += bv.y;
        acc[nn][2] += bv.x; acc[nn][3] += bv.y;
        s0 += acc[nn][0] + acc[nn][1];
        q0 += acc[nn][0] * acc[nn][0] + acc[nn][1] * acc[nn][1];
        s1 += acc[nn][2] + acc[nn][3];
        q1 += acc[nn][2] * acc[nn][2] + acc[nn][3] * acc[nn][3];
    }
#pragma unroll
    for (int m = 1; m < 4; m <<= 1) {
        s0 += __shfl_xor_sync(0xffffffffu, s0, m, 4);
        q0 += __shfl_xor_sync(0xffffffffu, q0, m, 4);
        s1 += __shfl_xor_sync(0xffffffffu, s1, m, 4);
        q1 += __shfl_xor_sync(0xffffffffu, q1, m, 4);
    }
    const float c = 1.0f / 32.0f;
    const float m0 = s0 * c, r0 = rsqrtf(fmaf(-m0, m0, q0 * c) + 1e-5f);
    const float m1 = s1 * c, r1 = rsqrtf(fmaf(-m1, m1, q1 * c) + 1e-5f);

    float y[4][4];
#pragma unroll
    for (int nn = 0; nn < 4; nn++) {
        float2 gv = *(const float2*)(gg + 8 * nn + 2 * t);
        float2 bv = *(const float2*)(bb + 8 * nn + 2 * t);
        float u;
        u = fmaf((acc[nn][0] - m0) * r0, gv.x, bv.x); y[nn][0] = fmaxf(u, 0.01f * u);
        u = fmaf((acc[nn][1] - m0) * r0, gv.y, bv.y); y[nn][1] = fmaxf(u, 0.01f * u);
        u = fmaf((acc[nn][2] - m1) * r1, gv.x, bv.x); y[nn][2] = fmaxf(u, 0.01f * u);
        u = fmaf((acc[nn][3] - m1) * r1, gv.y, bv.y); y[nn][3] = fmaxf(u, 0.01f * u);
    }
#pragma unroll
    for (int kk = 0; kk < 2; kk++) {
        split2(y[2 * kk][0],     y[2 * kk][1],     oh[kk][0], ol[kk][0]);
        split2(y[2 * kk][2],     y[2 * kk][3],     oh[kk][1], ol[kk][1]);
        split2(y[2 * kk + 1][0], y[2 * kk + 1][1], oh[kk][2], ol[kk][2]);
        split2(y[2 * kk + 1][2], y[2 * kk + 1][3], oh[kk][3], ol[kk][3]);
    }
}

__device__ __forceinline__ void loadx(const float* __restrict__ x, int tile, int g, int t,
                                      int nrows, float4 xa[4], float4 xb[4])
{
    const int r0 = tile * 16 + g, r1 = r0 + 8;
    const float* b0 = x + (size_t)r0 * 64 + 4 * t;
    const float* b1 = x + (size_t)r1 * 64 + 4 * t;
    const bool v0 = r0 < nrows, v1 = r1 < nrows;
#pragma unroll
    for (int kk = 0; kk < 4; kk++) {
        xa[kk] = v0 ? __ldcs((const float4*)(b0 + 16 * kk)) : make_float4(0.f, 0.f, 0.f, 0.f);
        xb[kk] = v1 ? __ldcs((const float4*)(b1 + 16 * kk)) : make_float4(0.f, 0.f, 0.f, 0.f);
    }
}

// ---------------- fused kernel: 1 warp per 16-row tile ----------------
__global__ void __launch_bounds__(128, 3)
fused_kernel(const float* __restrict__ x, float* __restrict__ out, int nrows, int ntiles)
{
    __shared__ uint4 w1s[512];            // GEMM1 frags  (8 KB)
    __shared__ uint4 w3s[512];            // GEMM3 frags  (8 KB)
    __shared__ float sp[192];             // ab | l1g | l1b | cb | l2g | l2b
    __shared__ float bos[64];             // bo (logical order)
    const int tid = threadIdx.x;
    {
        const uint4* s1 = (const uint4*)g_wp.w1;
        const uint4* s3 = (const uint4*)g_wp.w3;
        for (int i = tid; i < 512; i += 128) { w1s[i] = s1[i]; w3s[i] = s3[i]; }
        if (tid < 32) {
            sp[tid]       = g_wp.ab[tid];
            sp[32 + tid]  = g_wp.l1g[tid];
            sp[64 + tid]  = g_wp.l1b[tid];
            sp[96 + tid]  = g_wp.cb[tid];
            sp[128 + tid] = g_wp.l2g[tid];
            sp[160 + tid] = g_wp.l2b[tid];
        }
        if (tid < 64) bos[tid] = g_wp.bo[tid];
    }
    const int wid = tid >> 5, lane = tid & 31;
    const int g = lane >> 2, t = lane & 3;

    // GEMM2 weights persistent in registers (32 regs)
    uint4 w2r[2][4];
#pragma unroll
    for (int kk = 0; kk < 2; kk++)
#pragma unroll
        for (int nn = 0; nn < 4; nn++) w2r[kk][nn] = g_wp.w2[kk][nn][lane];
    __syncthreads();

    const int stride = gridDim.x * 4;
    int tile = blockIdx.x * 4 + wid;
    if (tile >= ntiles) return;

    float4 xa[4], xb[4];
    loadx(x, tile, g, t, nrows, xa, xb);

    for (; tile < ntiles; tile += stride) {
        // ---- convert current x to hi/lo A frags ----
        u32 ah[4][4], al[4][4];
#pragma unroll
        for (int kk = 0; kk < 4; kk++) {
            split2(xa[kk].x, xa[kk].y, ah[kk][0], al[kk][0]);
            split2(xb[kk].x, xb[kk].y, ah[kk][1], al[kk][1]);
            split2(xa[kk].z, xa[kk].w, ah[kk][2], al[kk][2]);
            split2(xb[kk].z, xb[kk].w, ah[kk][3], al[kk][3]);
        }
        if (tile + stride < ntiles) loadx(x, tile + stride, g, t, nrows, xa, xb);

        // ---- GEMM1: [16x64]@[64x32], weights from smem ----
        float acc[4][4];
#pragma unroll
        for (int nn = 0; nn < 4; nn++) {
            acc[nn][0] = acc[nn][1] = acc[nn][2] = acc[nn][3] = 0.f;
#pragma unroll
            for (int kk = 0; kk < 4; kk++) {
                uint4 w = w1s[(kk * 4 + nn) * 32 + lane];
                MMA(acc[nn], ah[kk][0], ah[kk][1], ah[kk][2], ah[kk][3], w.x, w.y);
                MMA(acc[nn], al[kk][0], al[kk][1], al[kk][2], al[kk][3], w.x, w.y);
                MMA(acc[nn], ah[kk][0], ah[kk][1], ah[kk][2], ah[kk][3], w.z, w.w);
            }
        }

        u32 a2h[2][4], a2l[2][4];
        ln_block(acc, sp + 0, sp + 32, sp + 64, t, a2h, a2l);

        // ---- GEMM2: [16x32]@[32x32], weights in regs ----
        float acc2[4][4];
#pragma unroll
        for (int nn = 0; nn < 4; nn++) {
            acc2[nn][0] = acc2[nn][1] = acc2[nn][2] = acc2[nn][3] = 0.f;
#pragma unroll
            for (int kk = 0; kk < 2; kk++) {
                uint4 w = w2r[kk][nn];
                MMA(acc2[nn], a2h[kk][0], a2h[kk][1], a2h[kk][2], a2h[kk][3], w.x, w.y);
                MMA(acc2[nn], a2l[kk][0], a2l[kk][1], a2l[kk][2], a2l[kk][3], w.x, w.y);
                MMA(acc2[nn], a2h[kk][0], a2h[kk][1], a2h[kk][2], a2h[kk][3], w.z, w.w);
            }
        }

        u32 a3h[2][4], a3l[2][4];
        ln_block(acc2, sp + 96, sp + 128, sp + 160, t, a3h, a3l);

        // ---- GEMM3: [16x32]@[32x64], weights from smem, store-permuted cols ----
        float acc3[8][4];
#pragma unroll
        for (int nn = 0; nn < 8; nn++) {
            acc3[nn][0] = acc3[nn][1] = acc3[nn][2] = acc3[nn][3] = 0.f;
#pragma unroll
            for (int kk = 0; kk < 2; kk++) {
                uint4 w = w3s[(kk * 8 + nn) * 32 + lane];
                MMA(acc3[nn], a3h[kk][0], a3h[kk][1], a3h[kk][2], a3h[kk][3], w.x, w.y);
                MMA(acc3[nn], a3l[kk][0], a3l[kk][1], a3l[kk][2], a3l[kk][3], w.x, w.y);
                MMA(acc3[nn], a3h[kk][0], a3h[kk][1], a3h[kk][2], a3h[kk][3], w.z, w.w);
            }
        }

        // ---- + bo, stores: instr j writes float4 @ logical col 16j+4t ----
        const int r0 = tile * 16 + g, r1 = r0 + 8;
        float* o0 = out + (size_t)r0 * 64;
        float* o1 = out + (size_t)r1 * 64;
        const bool v0 = r0 < nrows, v1 = r1 < nrows;
#pragma unroll
        for (int j = 0; j < 4; j++) {
            float4 b = *(const float4*)(bos + 16 * j + 4 * t);
            if (v0) {
                float4 v;
                v.x = acc3[2 * j][0]     + b.x;
                v.y = acc3[2 * j][1]     + b.y;
                v.z = acc3[2 * j + 1][0] + b.z;
                v.w = acc3[2 * j + 1][1] + b.w;
                __stcs((float4*)(o0 + 16 * j + 4 * t), v);
            }
            if (v1) {
                float4 v;
                v.x = acc3[2 * j][2]     + b.x;
                v.y = acc3[2 * j][3]     + b.y;
                v.z = acc3[2 * j + 1][2] + b.z;
                v.w = acc3[2 * j + 1][3] + b.w;
                __stcs((float4*)(o1 + 16 * j + 4 * t), v);
            }
        }
    }
}

extern "C" void kernel_launch(void* const* d_in, const int* in_sizes, int n_in,
                              void* d_out, int out_size)
{
    const float* x   = (const float*)d_in[0];
    const float* w1  = (const float*)d_in[1];
    const float* b1  = (const float*)d_in[2];
    const float* wv1 = (const float*)d_in[7];
    const float* bv1 = (const float*)d_in[8];
    const float* g1  = (const float*)d_in[9];
    const float* l1g = (const float*)d_in[10];
    const float* l1b = (const float*)d_in[11];
    const float* w2  = (const float*)d_in[12];
    const float* b2  = (const float*)d_in[13];
    const float* wv2 = (const float*)d_in[18];
    const float* bv2 = (const float*)d_in[19];
    const float* g2  = (const float*)d_in[20];
    const float* l2g = (const float*)d_in[21];
    const float* l2b = (const float*)d_in[22];
    const float* wo  = (const float*)d_in[23];
    const float* bo  = (const float*)d_in[24];

    const int B = in_sizes[0] / 64;
    const int ntiles = (B + 15) / 16;

    prep_kernel<<<1, 256>>>(w1, b1, wv1, bv1, g1, l1g, l1b,
                            w2, b2, wv2, bv2, g2, l2g, l2b, wo, bo);

    int grid = 3 * 148;                       // 3 CTAs/SM x 4 warps, persistent
    int need = (ntiles + 3) / 4;
    if (grid > need) grid = need;
    fused_kernel<<<grid, 128>>>(x, (float*)d_out, B, ntiles);
}